// round 16
// baseline (speedup 1.0000x reference)
#include <cuda_runtime.h>

// Problem constants: B=8, N=2048, D=768, two tensors (H, doc_sents_h)
#define DDIM   768
#define NROWS  32768            // 2 * 8 * 2048 source rows
#define ROW4   512              // float4 per output row (2048/4)
#define P1_BLOCKS 1184          // 148 SMs * 8 blocks -> persistent, no wave tail
#define P1_WARPS  (P1_BLOCKS * 8)

// Scratch: s_src (bias folded in) and s_dst per (tensor, batch, n)
__device__ float g_src[NROWS];
__device__ float g_dst[NROWS];

// Phase 1, persistent grid-stride: each warp handles rows r, r+9472, ...
// Keeps every SM at max resident warps with continuous load pressure.
__global__ __launch_bounds__(256) void edge_phase1(
    const float* __restrict__ H,
    const float* __restrict__ Dh,
    const float* __restrict__ W,     // [2*DDIM]: wa then wb
    const float* __restrict__ bptr)  // [1]
{
    int warp = blockIdx.x * 8 + (threadIdx.x >> 5);   // 0..9471
    int lane = threadIdx.x & 31;

    const float4* Wa4 = (const float4*)W;
    const float4* Wb4 = (const float4*)(W + DDIM);
    float bias = __ldg(bptr);

    for (int r = warp; r < NROWS; r += P1_WARPS) {
        const float* X = (r < NROWS / 2) ? (H  + (size_t)r * DDIM)
                                         : (Dh + (size_t)(r - NROWS / 2) * DDIM);
        const float4* X4 = (const float4*)X;

        float sa = 0.f, sb = 0.f;
        #pragma unroll
        for (int k = 0; k < 6; k++) {                 // 192 float4 per row / 32 lanes
            int idx = lane + k * 32;
            float4 x  = __ldcs(&X4[idx]);
            float4 wa = __ldg(&Wa4[idx]);
            float4 wb = __ldg(&Wb4[idx]);
            sa = fmaf(x.x, wa.x, fmaf(x.y, wa.y, fmaf(x.z, wa.z, fmaf(x.w, wa.w, sa))));
            sb = fmaf(x.x, wb.x, fmaf(x.y, wb.y, fmaf(x.z, wb.z, fmaf(x.w, wb.w, sb))));
        }
        #pragma unroll
        for (int off = 16; off; off >>= 1) {
            sa += __shfl_xor_sync(0xffffffffu, sa, off);
            sb += __shfl_xor_sync(0xffffffffu, sb, off);
        }
        if (lane == 0) {
            g_src[r] = sa + bias;
            g_dst[r] = sb;
        }
    }
}

// Phase 2 (R7 champion body, untouched): each block writes 1024 CONSECUTIVE
// float4 (16 KB), streaming stores.
__global__ __launch_bounds__(256) void edge_phase2(float4* __restrict__ out)
{
    const float*  __restrict__ src  = g_src;
    const float4* __restrict__ dst4 = (const float4*)g_dst;

    unsigned base = blockIdx.x * 1024u;               // 16384 blocks
    #pragma unroll
    for (int it = 0; it < 4; it++) {
        unsigned v   = base + it * 256u + threadIdx.x;
        unsigned row = v >> 9;                        // /ROW4
        unsigned j4  = v & (ROW4 - 1);
        float  si = __ldg(&src[row]);
        float4 sd = __ldg(&dst4[((row >> 11) << 9) + j4]);  // group = row/2048
        float4 o;
        o.x = fmaxf(si + sd.x, 0.f);
        o.y = fmaxf(si + sd.y, 0.f);
        o.z = fmaxf(si + sd.z, 0.f);
        o.w = fmaxf(si + sd.w, 0.f);
        __stcs(&out[v], o);
    }
}

extern "C" void kernel_launch(void* const* d_in, const int* in_sizes, int n_in,
                              void* d_out, int out_size)
{
    const float* H  = (const float*)d_in[0];
    const float* Dh = (const float*)d_in[1];
    const float* W  = (const float*)d_in[2];
    const float* b  = (const float*)d_in[3];
    float4* out = (float4*)d_out;

    edge_phase1<<<P1_BLOCKS, 256>>>(H, Dh, W, b);  // persistent grid-stride
    edge_phase2<<<16384, 256>>>(out);              // contiguous 16 KB per block
}

// round 17
// speedup vs baseline: 1.0651x; 1.0651x over previous
#include <cuda_runtime.h>
#include <cstdint>

// Problem constants: B=8, N=2048, D=768, two tensors (H, doc_sents_h)
#define DDIM   768
#define NROWS  32768            // 2 * 8 * 2048 source rows
#define ROW4   512              // float4 per output row (2048/4)

// Scratch: s_src (bias folded in) and s_dst per (tensor, batch, n)
__device__ float g_src[NROWS];
__device__ float g_dst[NROWS];

// Phase 1 (R7 champion body): one warp per row, both dots in one pass.
__global__ __launch_bounds__(256) void edge_phase1(
    const float* __restrict__ H,
    const float* __restrict__ Dh,
    const float* __restrict__ W,     // [2*DDIM]: wa then wb
    const float* __restrict__ bptr)  // [1]
{
    int r    = blockIdx.x * 8 + (threadIdx.x >> 5);   // row 0..32767
    int lane = threadIdx.x & 31;

    const float* X = (r < NROWS / 2) ? (H  + (size_t)r * DDIM)
                                     : (Dh + (size_t)(r - NROWS / 2) * DDIM);
    const float4* X4  = (const float4*)X;
    const float4* Wa4 = (const float4*)W;
    const float4* Wb4 = (const float4*)(W + DDIM);

    float sa = 0.f, sb = 0.f;
    #pragma unroll
    for (int k = 0; k < 6; k++) {                     // 192 float4 per row / 32 lanes
        int idx = lane + k * 32;
        float4 x  = __ldcs(&X4[idx]);
        float4 wa = __ldg(&Wa4[idx]);
        float4 wb = __ldg(&Wb4[idx]);
        sa = fmaf(x.x, wa.x, fmaf(x.y, wa.y, fmaf(x.z, wa.z, fmaf(x.w, wa.w, sa))));
        sb = fmaf(x.x, wb.x, fmaf(x.y, wb.y, fmaf(x.z, wb.z, fmaf(x.w, wb.w, sb))));
    }
    #pragma unroll
    for (int off = 16; off; off >>= 1) {
        sa += __shfl_xor_sync(0xffffffffu, sa, off);
        sb += __shfl_xor_sync(0xffffffffu, sb, off);
    }
    if (lane == 0) {
        g_src[r] = sa + __ldg(bptr);   // fold bias into the src term
        g_dst[r] = sb;
    }
}

// Phase 2 with TMA bulk store: compute the block's 16 KB tile in SMEM, then
// one cp.async.bulk (smem -> global via async proxy). Eliminates all STG L1
// wavefronts; loads and store addresses identical to the 39.4us kernel.
__global__ __launch_bounds__(256) void edge_phase2(float4* __restrict__ out)
{
    __shared__ alignas(128) float4 tile[1024];        // 16 KB

    const float*  __restrict__ src  = g_src;
    const float4* __restrict__ dst4 = (const float4*)g_dst;

    unsigned tid  = threadIdx.x;
    unsigned base = blockIdx.x * 1024u;               // 16384 blocks
    #pragma unroll
    for (int it = 0; it < 4; it++) {
        unsigned v   = base + it * 256u + tid;
        unsigned row = v >> 9;                        // /ROW4
        unsigned j4  = v & (ROW4 - 1);
        float  si = __ldg(&src[row]);
        float4 sd = __ldg(&dst4[((row >> 11) << 9) + j4]);  // group = row/2048
        float4 o;
        o.x = fmaxf(si + sd.x, 0.f);
        o.y = fmaxf(si + sd.y, 0.f);
        o.z = fmaxf(si + sd.z, 0.f);
        o.w = fmaxf(si + sd.w, 0.f);
        tile[it * 256 + tid] = o;
    }
    __syncthreads();

    if (tid == 0) {
        // Make generic-proxy smem writes visible to the async proxy.
        asm volatile("fence.proxy.async.shared::cta;" ::: "memory");
        uint32_t saddr;
        asm("{ .reg .u64 t; cvta.to.shared.u64 t, %1; cvt.u32.u64 %0, t; }"
            : "=r"(saddr) : "l"(tile));
        uint64_t gaddr = (uint64_t)(out + base);
        asm volatile(
            "cp.async.bulk.global.shared::cta.bulk_group [%0], [%1], %2;"
            :: "l"(gaddr), "r"(saddr), "r"(16384) : "memory");
        asm volatile("cp.async.bulk.commit_group;" ::: "memory");
        asm volatile("cp.async.bulk.wait_group.read 0;" ::: "memory");
    }
    __syncthreads();   // keep smem alive until the bulk read completes
}

extern "C" void kernel_launch(void* const* d_in, const int* in_sizes, int n_in,
                              void* d_out, int out_size)
{
    const float* H  = (const float*)d_in[0];
    const float* Dh = (const float*)d_in[1];
    const float* W  = (const float*)d_in[2];
    const float* b  = (const float*)d_in[3];
    float4* out = (float4*)d_out;

    edge_phase1<<<4096, 256>>>(H, Dh, W, b);   // 32768 rows, 8 warps/block
    edge_phase2<<<16384, 256>>>(out);          // 16 KB TMA bulk store per block
}